// round 3
// baseline (speedup 1.0000x reference)
#include <cuda_runtime.h>

#define TPB    512
#define NWARP  16
#define RR     4          // rows per warp
#define DD     64
#define HH     256
#define NPS    10
#define W2T_LD   257      // W2t[d][h] row stride (odd -> conflict-free lane-striped reads)
#define W1UT_LD  66       // W1uT[h][d] row stride (even -> 8B-aligned float2 at d=2*lane)

#define SMEM_FLOATS (DD*W2T_LD + HH*W1UT_LD + NWARP*HH*RR + NWARP*DD*RR)

__global__ __launch_bounds__(TPB, 1)
void iresblock_kernel(const float* __restrict__ gx,  const float* __restrict__ gu,
                      const float* __restrict__ glp, const float* __restrict__ gve,
                      const float* __restrict__ gW1x,const float* __restrict__ gW1u,
                      const float* __restrict__ gb1, const float* __restrict__ gW2,
                      const float* __restrict__ gb2, float* __restrict__ out, int B)
{
    extern __shared__ float sm[];
    float* sW2t  = sm;                        // [DD][W2T_LD]  : W2t[d][h] = W2[h][d]
    float* sW1uT = sW2t + DD*W2T_LD;          // [HH][W1UT_LD] : W1uT[h][d] = W1u[d][h]
    float* sYall = sW1uT + HH*W1UT_LD;        // [NWARP][HH][RR] staging (rows / ha / y)
    float* sWall = sYall + NWARP*HH*RR;       // [NWARP][DD][RR] staging (w)

    const int tid = threadIdx.x;

    // Load weights, transposed, into shared (coalesced global reads).
    for (int idx = tid; idx < HH*DD; idx += TPB) {
        int h = idx >> 6, d = idx & 63;
        sW2t[d*W2T_LD + h] = gW2[idx];        // W2 is [H][D] row-major
    }
    for (int idx = tid; idx < DD*HH; idx += TPB) {
        int d = idx >> 8, h = idx & 255;
        sW1uT[h*W1UT_LD + d] = gW1u[idx];     // W1u is [D][H] row-major
    }
    __syncthreads();

    const int warp = tid >> 5, lane = tid & 31;
    float* sY = sYall + warp*(HH*RR);         // [h][RR]
    float* sW = sWall + warp*(DD*RR);         // [d][RR]
    const int row0 = blockIdx.x*(NWARP*RR) + warp*RR;

    const float2* x2 = (const float2*)gx;
    const float2* u2 = (const float2*)gu;
    const float2* e2 = (const float2*)gve;
    float2* ox2 = (float2*)out;

    // ---- stage rows into sY (x at h 0..63, u at 64..127, ve at 128..191), copy x out
    float2 veR[RR];
    #pragma unroll
    for (int r = 0; r < RR; r++) {
        size_t row = (size_t)(row0 + r);
        float2 xv = x2[row*32 + lane];
        float2 uv = u2[row*32 + lane];
        float2 vv = e2[row*32 + lane];
        veR[r] = vv;
        ox2[row*32 + lane] = xv;              // output[0]: x passthrough
        sY[(2*lane  )*RR + r] = xv.x;
        sY[(2*lane+1)*RR + r] = xv.y;
        sY[(64 + 2*lane  )*RR + r] = uv.x;
        sY[(64 + 2*lane+1)*RR + r] = uv.y;
        sY[(128+ 2*lane  )*RR + r] = vv.x;
        sY[(128+ 2*lane+1)*RR + r] = vv.y;
    }
    __syncwarp();

    // ---- z[h] = sum_d x[d]W1x[d][h] + u[d]W1u[d][h]   (h = lane + 32*i)
    float zac[8][RR];
    #pragma unroll
    for (int i = 0; i < 8; i++)
        #pragma unroll
        for (int r = 0; r < RR; r++) zac[i][r] = 0.f;

    #pragma unroll 4
    for (int d = 0; d < DD; d++) {
        float wx[8], wu[8];
        #pragma unroll
        for (int i = 0; i < 8; i++) {
            wx[i] = __ldg(gW1x + d*HH + lane + 32*i);
            wu[i] = sW1uT[(lane + 32*i)*W1UT_LD + d];
        }
        float4 xb = *(const float4*)(sY + d*RR);
        float4 ub = *(const float4*)(sY + (64+d)*RR);
        float xa[4] = {xb.x, xb.y, xb.z, xb.w};
        float ua[4] = {ub.x, ub.y, ub.z, ub.w};
        #pragma unroll
        for (int i = 0; i < 8; i++)
            #pragma unroll
            for (int r = 0; r < RR; r++)
                zac[i][r] = fmaf(ua[r], wu[i], fmaf(xa[r], wx[i], zac[i][r]));
    }

    // ---- p1[h] = sum_d ve[d] * W2t[d][h]   (= ve @ W2^T)
    float pac[8][RR];
    #pragma unroll
    for (int i = 0; i < 8; i++)
        #pragma unroll
        for (int r = 0; r < RR; r++) pac[i][r] = 0.f;

    #pragma unroll 4
    for (int d = 0; d < DD; d++) {
        float wt[8];
        #pragma unroll
        for (int i = 0; i < 8; i++) wt[i] = sW2t[d*W2T_LD + lane + 32*i];
        float4 vb = *(const float4*)(sY + (128+d)*RR);
        float va[4] = {vb.x, vb.y, vb.z, vb.w};
        #pragma unroll
        for (int i = 0; i < 8; i++)
            #pragma unroll
            for (int r = 0; r < RR; r++)
                pac[i][r] = fmaf(va[r], wt[i], pac[i][r]);
    }
    __syncwarp();

    // ---- activation: s = elu'(z) kept in zac; ha = elu(z) staged to sY
    {
        float b1v[8];
        #pragma unroll
        for (int i = 0; i < 8; i++) b1v[i] = __ldg(gb1 + lane + 32*i);
        #pragma unroll
        for (int i = 0; i < 8; i++) {
            #pragma unroll
            for (int r = 0; r < RR; r++) {
                float z = zac[i][r] + b1v[i];
                float e = __expf(z);
                bool pos = (z > 0.f);
                zac[i][r] = pos ? 1.f : e;                  // s = elu'(z)
                sY[(lane + 32*i)*RR + r] = pos ? z : (e - 1.f);  // ha = elu(z)
            }
        }
    }
    __syncwarp();

    // ---- g[d] = sum_h ha[h] * W2[h][d] ; v = u + g + b2  (d = 2*lane, 2*lane+1)
    {
        float g0[RR], g1[RR];
        #pragma unroll
        for (int r = 0; r < RR; r++) { g0[r] = 0.f; g1[r] = 0.f; }
        #pragma unroll 4
        for (int h = 0; h < HH; h++) {
            float wa = sW2t[(2*lane  )*W2T_LD + h];
            float wb = sW2t[(2*lane+1)*W2T_LD + h];
            float4 hb = *(const float4*)(sY + h*RR);
            float ha4[4] = {hb.x, hb.y, hb.z, hb.w};
            #pragma unroll
            for (int r = 0; r < RR; r++) {
                g0[r] = fmaf(ha4[r], wa, g0[r]);
                g1[r] = fmaf(ha4[r], wb, g1[r]);
            }
        }
        float2 b2v = ((const float2*)gb2)[lane];
        float2* ov2 = (float2*)(out + (size_t)B*DD);
        #pragma unroll
        for (int r = 0; r < RR; r++) {
            size_t row = (size_t)(row0 + r);
            float2 uv = u2[row*32 + lane];
            float2 vo;
            vo.x = uv.x + g0[r] + b2v.x;
            vo.y = uv.y + g1[r] + b2v.y;
            ov2[row*32 + lane] = vo;            // output[1]: v = u + g
        }
    }

    // ---- power series: for k=1..10: y=p*s; w=y@W1u^T; dot=w.ve; p=w@W2^T
    float lgd[RR] = {0.f, 0.f, 0.f, 0.f};
    #pragma unroll 1
    for (int k = 0; k < NPS; k++) {
        __syncwarp();
        // stage y = p .* s  into sY[h][r]
        #pragma unroll
        for (int i = 0; i < 8; i++) {
            float4 yv;
            yv.x = pac[i][0]*zac[i][0];
            yv.y = pac[i][1]*zac[i][1];
            yv.z = pac[i][2]*zac[i][2];
            yv.w = pac[i][3]*zac[i][3];
            *(float4*)(sY + (lane + 32*i)*RR) = yv;
        }
        __syncwarp();

        // w[d] = sum_h y[h] * W1uT[h][d]   (d = 2*lane, 2*lane+1)
        float w0[RR] = {0.f,0.f,0.f,0.f}, w1[RR] = {0.f,0.f,0.f,0.f};
        #pragma unroll 4
        for (int h = 0; h < HH; h++) {
            float2 wv = *(const float2*)(sW1uT + h*W1UT_LD + 2*lane);
            float4 yb = *(const float4*)(sY + h*RR);
            float ya[4] = {yb.x, yb.y, yb.z, yb.w};
            #pragma unroll
            for (int r = 0; r < RR; r++) {
                w0[r] = fmaf(ya[r], wv.x, w0[r]);
                w1[r] = fmaf(ya[r], wv.y, w1[r]);
            }
        }

        // dot_k = w . vareps ; logdet += coeff_k * dot_k
        float ck = ((k & 1) ? -1.f : 1.f) / (float)(k + 1);
        #pragma unroll
        for (int r = 0; r < RR; r++) {
            float part = w0[r]*veR[r].x + w1[r]*veR[r].y;
            part += __shfl_xor_sync(0xffffffffu, part, 16);
            part += __shfl_xor_sync(0xffffffffu, part, 8);
            part += __shfl_xor_sync(0xffffffffu, part, 4);
            part += __shfl_xor_sync(0xffffffffu, part, 2);
            part += __shfl_xor_sync(0xffffffffu, part, 1);
            lgd[r] += ck * part;
        }

        if (k < NPS - 1) {
            __syncwarp();
            float4 a0, a1;
            a0.x = w0[0]; a0.y = w0[1]; a0.z = w0[2]; a0.w = w0[3];
            a1.x = w1[0]; a1.y = w1[1]; a1.z = w1[2]; a1.w = w1[3];
            *(float4*)(sW + (2*lane  )*RR) = a0;
            *(float4*)(sW + (2*lane+1)*RR) = a1;
            __syncwarp();

            // p[h] = sum_d w[d] * W2t[d][h]
            #pragma unroll
            for (int i = 0; i < 8; i++)
                #pragma unroll
                for (int r = 0; r < RR; r++) pac[i][r] = 0.f;

            #pragma unroll 4
            for (int d = 0; d < DD; d++) {
                float wt[8];
                #pragma unroll
                for (int i = 0; i < 8; i++) wt[i] = sW2t[d*W2T_LD + lane + 32*i];
                float4 wb4 = *(const float4*)(sW + d*RR);
                float wa4[4] = {wb4.x, wb4.y, wb4.z, wb4.w};
                #pragma unroll
                for (int i = 0; i < 8; i++)
                    #pragma unroll
                    for (int r = 0; r < RR; r++)
                        pac[i][r] = fmaf(wa4[r], wt[i], pac[i][r]);
            }
        }
    }

    // ---- output[2]: logpx - logdet
    if (lane == 0) {
        float* olp = out + (size_t)2*B*DD;
        #pragma unroll
        for (int r = 0; r < RR; r++) {
            int row = row0 + r;
            olp[row] = glp[row] - lgd[r];
        }
    }
}

extern "C" void kernel_launch(void* const* d_in, const int* in_sizes, int n_in,
                              void* d_out, int out_size)
{
    const float* gx   = (const float*)d_in[0];
    const float* gu   = (const float*)d_in[1];
    const float* glp  = (const float*)d_in[2];
    const float* gve  = (const float*)d_in[3];
    const float* gW1x = (const float*)d_in[4];
    const float* gW1u = (const float*)d_in[5];
    const float* gb1  = (const float*)d_in[6];
    const float* gW2  = (const float*)d_in[7];
    const float* gb2  = (const float*)d_in[8];
    float* out = (float*)d_out;

    int B = in_sizes[0] / DD;                 // 131072
    int grid = B / (NWARP*RR);                // 2048

    size_t smem = (size_t)SMEM_FLOATS * sizeof(float);   // ~215 KB
    cudaFuncSetAttribute(iresblock_kernel,
                         cudaFuncAttributeMaxDynamicSharedMemorySize, (int)smem);

    iresblock_kernel<<<grid, TPB, smem>>>(gx, gu, glp, gve, gW1x, gW1u,
                                          gb1, gW2, gb2, out, B);
}

// round 4
// speedup vs baseline: 1.1091x; 1.1091x over previous
#include <cuda_runtime.h>

#define TPB    256
#define NWARP  8
#define RR     8          // rows per warp (packed as 4 f32x2 pairs)
#define DD     64
#define HH     256
#define NPS    10
#define W2T_LD   257      // W2t[d][h] stride (odd -> conflict-free lane-striped)
#define W1UT_LD  66       // W1uT[h][d] stride (even -> aligned float2 at d=2*lane)
#define YLD      8        // floats per h slot in staging

#define SMEM_FLOATS (DD*W2T_LD + HH*W1UT_LD + NWARP*HH*YLD + NWARP*DD*YLD)

typedef unsigned long long ull;

__device__ __forceinline__ ull pack2(float lo, float hi) {
    ull r; asm("mov.b64 %0,{%1,%2};" : "=l"(r)
               : "r"(__float_as_uint(lo)), "r"(__float_as_uint(hi)));
    return r;
}
__device__ __forceinline__ void unpack2(ull v, float& lo, float& hi) {
    unsigned a, b; asm("mov.b64 {%0,%1},%2;" : "=r"(a), "=r"(b) : "l"(v));
    lo = __uint_as_float(a); hi = __uint_as_float(b);
}
__device__ __forceinline__ ull dup2(float x) { return pack2(x, x); }
__device__ __forceinline__ ull fma2(ull a, ull b, ull c) {
    ull d; asm("fma.rn.f32x2 %0,%1,%2,%3;" : "=l"(d) : "l"(a), "l"(b), "l"(c));
    return d;
}
__device__ __forceinline__ ull mul2(ull a, ull b) {
    ull d; asm("mul.rn.f32x2 %0,%1,%2;" : "=l"(d) : "l"(a), "l"(b));
    return d;
}

__global__ __launch_bounds__(TPB, 1)
void iresblock_kernel(const float* __restrict__ gx,  const float* __restrict__ gu,
                      const float* __restrict__ glp, const float* __restrict__ gve,
                      const float* __restrict__ gW1x,const float* __restrict__ gW1u,
                      const float* __restrict__ gb1, const float* __restrict__ gW2,
                      const float* __restrict__ gb2, float* __restrict__ out, int B)
{
    extern __shared__ float sm[];
    float* sW2t  = sm;                        // [DD][W2T_LD]  W2t[d][h] = W2[h][d]
    float* sW1uT = sW2t + DD*W2T_LD;          // [HH][W1UT_LD] W1uT[h][d] = W1u[d][h]
    float* sYall = sW1uT + HH*W1UT_LD;        // [NWARP][HH][YLD] staging
    float* sWall = sYall + NWARP*HH*YLD;      // [NWARP][DD][YLD] staging

    const int tid = threadIdx.x;

    for (int idx = tid; idx < HH*DD; idx += TPB) {
        int h = idx >> 6, d = idx & 63;
        sW2t[d*W2T_LD + h] = gW2[idx];        // W2 is [H][D] row-major
    }
    for (int idx = tid; idx < DD*HH; idx += TPB) {
        int d = idx >> 8, h = idx & 255;
        sW1uT[h*W1UT_LD + d] = gW1u[idx];     // W1u is [D][H] row-major
    }
    __syncthreads();

    const int warp = tid >> 5, lane = tid & 31;
    float* sY = sYall + warp*(HH*YLD);
    float* sW = sWall + warp*(DD*YLD);
    const int row0 = blockIdx.x*(NWARP*RR) + warp*RR;

    const float2* x2 = (const float2*)gx;
    const float2* u2 = (const float2*)gu;
    const float2* e2 = (const float2*)gve;
    float2* ox2 = (float2*)out;

    // ---- stage rows (x at h 0..63, u at 64..127, ve at 128..191); x passthrough
    ull vexp[4], veyp[4];
    {
        float vx[RR], vy[RR];
        #pragma unroll
        for (int r = 0; r < RR; r++) {
            size_t row = (size_t)(row0 + r);
            float2 xv = x2[row*32 + lane];
            float2 uv = u2[row*32 + lane];
            float2 vv = e2[row*32 + lane];
            ox2[row*32 + lane] = xv;
            sY[(2*lane  )*YLD + r] = xv.x;
            sY[(2*lane+1)*YLD + r] = xv.y;
            sY[(64 + 2*lane  )*YLD + r] = uv.x;
            sY[(64 + 2*lane+1)*YLD + r] = uv.y;
            sY[(128+ 2*lane  )*YLD + r] = vv.x;
            sY[(128+ 2*lane+1)*YLD + r] = vv.y;
            vx[r] = vv.x; vy[r] = vv.y;
        }
        #pragma unroll
        for (int j = 0; j < 4; j++) {
            vexp[j] = pack2(vx[2*j], vx[2*j+1]);
            veyp[j] = pack2(vy[2*j], vy[2*j+1]);
        }
    }
    __syncwarp();

    // ---- z[h] = sum_d x[d]W1x[d][h] + u[d]W1u[d][h]   (h = lane+32i, rows packed)
    ull zac[8][4];
    #pragma unroll
    for (int i = 0; i < 8; i++)
        #pragma unroll
        for (int j = 0; j < 4; j++) zac[i][j] = 0ull;

    #pragma unroll 2
    for (int d = 0; d < DD; d++) {
        ull wxp[8], wup[8];
        #pragma unroll
        for (int i = 0; i < 8; i++) {
            wxp[i] = dup2(__ldg(gW1x + d*HH + lane + 32*i));
            wup[i] = dup2(sW1uT[(lane + 32*i)*W1UT_LD + d]);
        }
        ulonglong2 xa = *(const ulonglong2*)(sY + d*YLD);
        ulonglong2 xb = *(const ulonglong2*)(sY + d*YLD + 4);
        ulonglong2 ua = *(const ulonglong2*)(sY + (64+d)*YLD);
        ulonglong2 ub = *(const ulonglong2*)(sY + (64+d)*YLD + 4);
        ull xp[4] = {xa.x, xa.y, xb.x, xb.y};
        ull up[4] = {ua.x, ua.y, ub.x, ub.y};
        #pragma unroll
        for (int i = 0; i < 8; i++)
            #pragma unroll
            for (int j = 0; j < 4; j++)
                zac[i][j] = fma2(up[j], wup[i], fma2(xp[j], wxp[i], zac[i][j]));
    }

    // ---- p1[h] = sum_d ve[d] * W2t[d][h]
    ull pac[8][4];
    #pragma unroll
    for (int i = 0; i < 8; i++)
        #pragma unroll
        for (int j = 0; j < 4; j++) pac[i][j] = 0ull;

    #pragma unroll 2
    for (int d = 0; d < DD; d++) {
        ull wtp[8];
        #pragma unroll
        for (int i = 0; i < 8; i++) wtp[i] = dup2(sW2t[d*W2T_LD + lane + 32*i]);
        ulonglong2 va = *(const ulonglong2*)(sY + (128+d)*YLD);
        ulonglong2 vb = *(const ulonglong2*)(sY + (128+d)*YLD + 4);
        ull vp[4] = {va.x, va.y, vb.x, vb.y};
        #pragma unroll
        for (int i = 0; i < 8; i++)
            #pragma unroll
            for (int j = 0; j < 4; j++)
                pac[i][j] = fma2(vp[j], wtp[i], pac[i][j]);
    }
    __syncwarp();

    // ---- activation: s = elu'(z) kept packed in zac; ha = elu(z) staged to sY
    #pragma unroll
    for (int i = 0; i < 8; i++) {
        float b1v = __ldg(gb1 + lane + 32*i);
        float ha[8];
        #pragma unroll
        for (int j = 0; j < 4; j++) {
            float z0, z1; unpack2(zac[i][j], z0, z1);
            z0 += b1v; z1 += b1v;
            float e0 = __expf(z0), e1 = __expf(z1);
            float s0 = (z0 > 0.f) ? 1.f : e0;
            float s1 = (z1 > 0.f) ? 1.f : e1;
            ha[2*j  ] = (z0 > 0.f) ? z0 : (e0 - 1.f);
            ha[2*j+1] = (z1 > 0.f) ? z1 : (e1 - 1.f);
            zac[i][j] = pack2(s0, s1);
        }
        ulonglong2 h01, h23;
        h01.x = pack2(ha[0], ha[1]); h01.y = pack2(ha[2], ha[3]);
        h23.x = pack2(ha[4], ha[5]); h23.y = pack2(ha[6], ha[7]);
        *(ulonglong2*)(sY + (lane + 32*i)*YLD    ) = h01;
        *(ulonglong2*)(sY + (lane + 32*i)*YLD + 4) = h23;
    }
    __syncwarp();

    // ---- g[d] = sum_h ha[h]*W2[h][d]; v = u + g + b2  (weights from global, L1-hot)
    {
        ull g0[4] = {0,0,0,0}, g1[4] = {0,0,0,0};
        #pragma unroll 8
        for (int h = 0; h < HH; h++) {
            float2 wv = __ldg((const float2*)(gW2 + h*DD) + lane);
            ull wa = dup2(wv.x), wb = dup2(wv.y);
            ulonglong2 ya = *(const ulonglong2*)(sY + h*YLD);
            ulonglong2 yb = *(const ulonglong2*)(sY + h*YLD + 4);
            ull yp[4] = {ya.x, ya.y, yb.x, yb.y};
            #pragma unroll
            for (int j = 0; j < 4; j++) {
                g0[j] = fma2(yp[j], wa, g0[j]);
                g1[j] = fma2(yp[j], wb, g1[j]);
            }
        }
        float2 b2v = __ldg(((const float2*)gb2) + lane);
        float2* ov2 = (float2*)(out + (size_t)B*DD);
        #pragma unroll
        for (int j = 0; j < 4; j++) {
            float a0, a1, b0, b1_;
            unpack2(g0[j], a0, a1);
            unpack2(g1[j], b0, b1_);
            {
                size_t row = (size_t)(row0 + 2*j);
                float2 uv = u2[row*32 + lane];
                float2 vo; vo.x = uv.x + a0 + b2v.x; vo.y = uv.y + b0 + b2v.y;
                ov2[row*32 + lane] = vo;
            }
            {
                size_t row = (size_t)(row0 + 2*j + 1);
                float2 uv = u2[row*32 + lane];
                float2 vo; vo.x = uv.x + a1 + b2v.x; vo.y = uv.y + b1_ + b2v.y;
                ov2[row*32 + lane] = vo;
            }
        }
    }

    // ---- power series
    ull lgdp[4] = {0,0,0,0};
    #pragma unroll 1
    for (int k = 0; k < NPS; k++) {
        __syncwarp();
        // stage y = p .* s
        #pragma unroll
        for (int i = 0; i < 8; i++) {
            ulonglong2 y01, y23;
            y01.x = mul2(pac[i][0], zac[i][0]);
            y01.y = mul2(pac[i][1], zac[i][1]);
            y23.x = mul2(pac[i][2], zac[i][2]);
            y23.y = mul2(pac[i][3], zac[i][3]);
            *(ulonglong2*)(sY + (lane + 32*i)*YLD    ) = y01;
            *(ulonglong2*)(sY + (lane + 32*i)*YLD + 4) = y23;
        }
        __syncwarp();

        // w[d] = sum_h y[h] * W1uT[h][d]   (d = 2*lane, 2*lane+1)
        ull w0p[4] = {0,0,0,0}, w1p[4] = {0,0,0,0};
        #pragma unroll 8
        for (int h = 0; h < HH; h++) {
            float2 wv = *(const float2*)(sW1uT + h*W1UT_LD + 2*lane);
            ull wa = dup2(wv.x), wb = dup2(wv.y);
            ulonglong2 ya = *(const ulonglong2*)(sY + h*YLD);
            ulonglong2 yb = *(const ulonglong2*)(sY + h*YLD + 4);
            w0p[0] = fma2(ya.x, wa, w0p[0]);  w1p[0] = fma2(ya.x, wb, w1p[0]);
            w0p[1] = fma2(ya.y, wa, w0p[1]);  w1p[1] = fma2(ya.y, wb, w1p[1]);
            w0p[2] = fma2(yb.x, wa, w0p[2]);  w1p[2] = fma2(yb.x, wb, w1p[2]);
            w0p[3] = fma2(yb.y, wa, w0p[3]);  w1p[3] = fma2(yb.y, wb, w1p[3]);
        }

        // logdet partial (per-lane, reduced after the loop)
        float ck = ((k & 1) ? -1.f : 1.f) / (float)(k + 1);
        ull ckp = dup2(ck);
        #pragma unroll
        for (int j = 0; j < 4; j++)
            lgdp[j] = fma2(ckp, fma2(w1p[j], veyp[j], mul2(w0p[j], vexp[j])), lgdp[j]);

        if (k < NPS - 1) {
            __syncwarp();
            ulonglong2 s0, s1, s2, s3;
            s0.x = w0p[0]; s0.y = w0p[1]; s1.x = w0p[2]; s1.y = w0p[3];
            s2.x = w1p[0]; s2.y = w1p[1]; s3.x = w1p[2]; s3.y = w1p[3];
            *(ulonglong2*)(sW + (2*lane  )*YLD    ) = s0;
            *(ulonglong2*)(sW + (2*lane  )*YLD + 4) = s1;
            *(ulonglong2*)(sW + (2*lane+1)*YLD    ) = s2;
            *(ulonglong2*)(sW + (2*lane+1)*YLD + 4) = s3;
            __syncwarp();

            // p[h] = sum_d w[d] * W2t[d][h]
            #pragma unroll
            for (int i = 0; i < 8; i++)
                #pragma unroll
                for (int j = 0; j < 4; j++) pac[i][j] = 0ull;

            #pragma unroll 4
            for (int d = 0; d < DD; d++) {
                ull wtp[8];
                #pragma unroll
                for (int i = 0; i < 8; i++) wtp[i] = dup2(sW2t[d*W2T_LD + lane + 32*i]);
                ulonglong2 wA = *(const ulonglong2*)(sW + d*YLD);
                ulonglong2 wB = *(const ulonglong2*)(sW + d*YLD + 4);
                ull wp[4] = {wA.x, wA.y, wB.x, wB.y};
                #pragma unroll
                for (int i = 0; i < 8; i++)
                    #pragma unroll
                    for (int j = 0; j < 4; j++)
                        pac[i][j] = fma2(wp[j], wtp[i], pac[i][j]);
            }
        }
    }

    // ---- reduce logdet partials over lanes; output[2]
    {
        float lgd[RR];
        #pragma unroll
        for (int j = 0; j < 4; j++) unpack2(lgdp[j], lgd[2*j], lgd[2*j+1]);
        #pragma unroll
        for (int r = 0; r < RR; r++) {
            float part = lgd[r];
            part += __shfl_xor_sync(0xffffffffu, part, 16);
            part += __shfl_xor_sync(0xffffffffu, part, 8);
            part += __shfl_xor_sync(0xffffffffu, part, 4);
            part += __shfl_xor_sync(0xffffffffu, part, 2);
            part += __shfl_xor_sync(0xffffffffu, part, 1);
            lgd[r] = part;
        }
        if (lane == 0) {
            float* olp = out + (size_t)2*B*DD;
            #pragma unroll
            for (int r = 0; r < RR; r++) {
                int row = row0 + r;
                olp[row] = glp[row] - lgd[r];
            }
        }
    }
}

extern "C" void kernel_launch(void* const* d_in, const int* in_sizes, int n_in,
                              void* d_out, int out_size)
{
    const float* gx   = (const float*)d_in[0];
    const float* gu   = (const float*)d_in[1];
    const float* glp  = (const float*)d_in[2];
    const float* gve  = (const float*)d_in[3];
    const float* gW1x = (const float*)d_in[4];
    const float* gW1u = (const float*)d_in[5];
    const float* gb1  = (const float*)d_in[6];
    const float* gW2  = (const float*)d_in[7];
    const float* gb2  = (const float*)d_in[8];
    float* out = (float*)d_out;

    int B = in_sizes[0] / DD;                 // 131072
    int grid = B / (NWARP*RR);                // 2048

    size_t smem = (size_t)SMEM_FLOATS * sizeof(float);   // ~210 KB
    cudaFuncSetAttribute(iresblock_kernel,
                         cudaFuncAttributeMaxDynamicSharedMemorySize, (int)smem);

    iresblock_kernel<<<grid, TPB, smem>>>(gx, gu, glp, gve, gW1x, gW1u,
                                          gb1, gW2, gb2, out, B);
}

// round 5
// speedup vs baseline: 1.1092x; 1.0002x over previous
#include <cuda_runtime.h>

#define TPB    256
#define NWARP  8
#define RR     8          // rows per warp (packed as 4 f32x2 pairs)
#define DD     64
#define HH     256
#define NPS    10
#define W2T_LD   257      // W2t[d][h] stride (odd -> conflict-free lane-striped)
#define W1UT_LD  66       // W1uT[h][d] stride (even -> aligned float2 at d=2*lane)
#define YLD      8        // floats per h slot in staging

#define SMEM_FLOATS (DD*W2T_LD + HH*W1UT_LD + NWARP*HH*YLD + NWARP*DD*YLD)

typedef unsigned long long ull;

__device__ __forceinline__ ull pack2(float lo, float hi) {
    ull r; asm("mov.b64 %0,{%1,%2};" : "=l"(r)
               : "r"(__float_as_uint(lo)), "r"(__float_as_uint(hi)));
    return r;
}
__device__ __forceinline__ void unpack2(ull v, float& lo, float& hi) {
    unsigned a, b; asm("mov.b64 {%0,%1},%2;" : "=r"(a), "=r"(b) : "l"(v));
    lo = __uint_as_float(a); hi = __uint_as_float(b);
}
__device__ __forceinline__ ull dup2(float x) { return pack2(x, x); }
__device__ __forceinline__ ull fma2(ull a, ull b, ull c) {
    ull d; asm("fma.rn.f32x2 %0,%1,%2,%3;" : "=l"(d) : "l"(a), "l"(b), "l"(c));
    return d;
}
__device__ __forceinline__ ull mul2(ull a, ull b) {
    ull d; asm("mul.rn.f32x2 %0,%1,%2;" : "=l"(d) : "l"(a), "l"(b));
    return d;
}

__global__ __launch_bounds__(TPB, 1)
void iresblock_kernel(const float* __restrict__ gx,  const float* __restrict__ gu,
                      const float* __restrict__ glp, const float* __restrict__ gve,
                      const float* __restrict__ gW1x,const float* __restrict__ gW1u,
                      const float* __restrict__ gb1, const float* __restrict__ gW2,
                      const float* __restrict__ gb2, float* __restrict__ out, int B)
{
    extern __shared__ float sm[];
    float* sW2t  = sm;                        // [DD][W2T_LD]  W2t[d][h] = W2[h][d]
    float* sW1uT = sW2t + DD*W2T_LD;          // [HH][W1UT_LD] W1uT[h][d] = W1u[d][h]
    float* sYall = sW1uT + HH*W1UT_LD;        // [NWARP][HH][YLD] staging
    float* sWall = sYall + NWARP*HH*YLD;      // [NWARP][DD][YLD] staging

    const int tid = threadIdx.x;

    for (int idx = tid; idx < HH*DD; idx += TPB) {
        int h = idx >> 6, d = idx & 63;
        sW2t[d*W2T_LD + h] = gW2[idx];        // W2 is [H][D] row-major
    }
    for (int idx = tid; idx < DD*HH; idx += TPB) {
        int d = idx >> 8, h = idx & 255;
        sW1uT[h*W1UT_LD + d] = gW1u[idx];     // W1u is [D][H] row-major
    }
    __syncthreads();

    const int warp = tid >> 5, lane = tid & 31;
    float* sY = sYall + warp*(HH*YLD);
    float* sW = sWall + warp*(DD*YLD);
    const int row0 = blockIdx.x*(NWARP*RR) + warp*RR;

    const float2* x2 = (const float2*)gx;
    const float2* u2 = (const float2*)gu;
    const float2* e2 = (const float2*)gve;
    float2* ox2 = (float2*)out;

    // ---- stage rows (x at h 0..63, u at 64..127, ve at 128..191); x passthrough
    ull vexp[4], veyp[4];
    {
        float vx[RR], vy[RR];
        #pragma unroll
        for (int r = 0; r < RR; r++) {
            size_t row = (size_t)(row0 + r);
            float2 xv = x2[row*32 + lane];
            float2 uv = u2[row*32 + lane];
            float2 vv = e2[row*32 + lane];
            ox2[row*32 + lane] = xv;
            sY[(2*lane  )*YLD + r] = xv.x;
            sY[(2*lane+1)*YLD + r] = xv.y;
            sY[(64 + 2*lane  )*YLD + r] = uv.x;
            sY[(64 + 2*lane+1)*YLD + r] = uv.y;
            sY[(128+ 2*lane  )*YLD + r] = vv.x;
            sY[(128+ 2*lane+1)*YLD + r] = vv.y;
            vx[r] = vv.x; vy[r] = vv.y;
        }
        #pragma unroll
        for (int j = 0; j < 4; j++) {
            vexp[j] = pack2(vx[2*j], vx[2*j+1]);
            veyp[j] = pack2(vy[2*j], vy[2*j+1]);
        }
    }
    __syncwarp();

    // ---- z[h] = sum_d x[d]W1x[d][h] + u[d]W1u[d][h]   (h = lane+32i, rows packed)
    ull zac[8][4];
    #pragma unroll
    for (int i = 0; i < 8; i++)
        #pragma unroll
        for (int j = 0; j < 4; j++) zac[i][j] = 0ull;

    #pragma unroll 2
    for (int d = 0; d < DD; d++) {
        ull wxp[8], wup[8];
        #pragma unroll
        for (int i = 0; i < 8; i++) {
            wxp[i] = dup2(__ldg(gW1x + d*HH + lane + 32*i));
            wup[i] = dup2(sW1uT[(lane + 32*i)*W1UT_LD + d]);
        }
        ulonglong2 xa = *(const ulonglong2*)(sY + d*YLD);
        ulonglong2 xb = *(const ulonglong2*)(sY + d*YLD + 4);
        ulonglong2 ua = *(const ulonglong2*)(sY + (64+d)*YLD);
        ulonglong2 ub = *(const ulonglong2*)(sY + (64+d)*YLD + 4);
        ull xp[4] = {xa.x, xa.y, xb.x, xb.y};
        ull up[4] = {ua.x, ua.y, ub.x, ub.y};
        #pragma unroll
        for (int i = 0; i < 8; i++)
            #pragma unroll
            for (int j = 0; j < 4; j++)
                zac[i][j] = fma2(up[j], wup[i], fma2(xp[j], wxp[i], zac[i][j]));
    }

    // ---- p1[h] = sum_d ve[d] * W2t[d][h]
    ull pac[8][4];
    #pragma unroll
    for (int i = 0; i < 8; i++)
        #pragma unroll
        for (int j = 0; j < 4; j++) pac[i][j] = 0ull;

    #pragma unroll 2
    for (int d = 0; d < DD; d++) {
        ull wtp[8];
        #pragma unroll
        for (int i = 0; i < 8; i++) wtp[i] = dup2(sW2t[d*W2T_LD + lane + 32*i]);
        ulonglong2 va = *(const ulonglong2*)(sY + (128+d)*YLD);
        ulonglong2 vb = *(const ulonglong2*)(sY + (128+d)*YLD + 4);
        ull vp[4] = {va.x, va.y, vb.x, vb.y};
        #pragma unroll
        for (int i = 0; i < 8; i++)
            #pragma unroll
            for (int j = 0; j < 4; j++)
                pac[i][j] = fma2(vp[j], wtp[i], pac[i][j]);
    }
    __syncwarp();

    // ---- activation: s = elu'(z) kept packed in zac; ha = elu(z) staged to sY
    #pragma unroll
    for (int i = 0; i < 8; i++) {
        float b1v = __ldg(gb1 + lane + 32*i);
        float ha[8];
        #pragma unroll
        for (int j = 0; j < 4; j++) {
            float z0, z1; unpack2(zac[i][j], z0, z1);
            z0 += b1v; z1 += b1v;
            float e0 = __expf(z0), e1 = __expf(z1);
            float s0 = (z0 > 0.f) ? 1.f : e0;
            float s1 = (z1 > 0.f) ? 1.f : e1;
            ha[2*j  ] = (z0 > 0.f) ? z0 : (e0 - 1.f);
            ha[2*j+1] = (z1 > 0.f) ? z1 : (e1 - 1.f);
            zac[i][j] = pack2(s0, s1);
        }
        ulonglong2 h01, h23;
        h01.x = pack2(ha[0], ha[1]); h01.y = pack2(ha[2], ha[3]);
        h23.x = pack2(ha[4], ha[5]); h23.y = pack2(ha[6], ha[7]);
        *(ulonglong2*)(sY + (lane + 32*i)*YLD    ) = h01;
        *(ulonglong2*)(sY + (lane + 32*i)*YLD + 4) = h23;
    }
    __syncwarp();

    // ---- g[d] = sum_h ha[h]*W2[h][d]; v = u + g + b2  (weights from global, L1-hot)
    {
        ull g0[4] = {0,0,0,0}, g1[4] = {0,0,0,0};
        #pragma unroll 8
        for (int h = 0; h < HH; h++) {
            float2 wv = __ldg((const float2*)(gW2 + h*DD) + lane);
            ull wa = dup2(wv.x), wb = dup2(wv.y);
            ulonglong2 ya = *(const ulonglong2*)(sY + h*YLD);
            ulonglong2 yb = *(const ulonglong2*)(sY + h*YLD + 4);
            ull yp[4] = {ya.x, ya.y, yb.x, yb.y};
            #pragma unroll
            for (int j = 0; j < 4; j++) {
                g0[j] = fma2(yp[j], wa, g0[j]);
                g1[j] = fma2(yp[j], wb, g1[j]);
            }
        }
        float2 b2v = __ldg(((const float2*)gb2) + lane);
        float2* ov2 = (float2*)(out + (size_t)B*DD);
        #pragma unroll
        for (int j = 0; j < 4; j++) {
            float a0, a1, b0, b1_;
            unpack2(g0[j], a0, a1);
            unpack2(g1[j], b0, b1_);
            {
                size_t row = (size_t)(row0 + 2*j);
                float2 uv = u2[row*32 + lane];
                float2 vo; vo.x = uv.x + a0 + b2v.x; vo.y = uv.y + b0 + b2v.y;
                ov2[row*32 + lane] = vo;
            }
            {
                size_t row = (size_t)(row0 + 2*j + 1);
                float2 uv = u2[row*32 + lane];
                float2 vo; vo.x = uv.x + a1 + b2v.x; vo.y = uv.y + b1_ + b2v.y;
                ov2[row*32 + lane] = vo;
            }
        }
    }

    // ---- power series
    ull lgdp[4] = {0,0,0,0};
    #pragma unroll 1
    for (int k = 0; k < NPS; k++) {
        __syncwarp();
        // stage y = p .* s
        #pragma unroll
        for (int i = 0; i < 8; i++) {
            ulonglong2 y01, y23;
            y01.x = mul2(pac[i][0], zac[i][0]);
            y01.y = mul2(pac[i][1], zac[i][1]);
            y23.x = mul2(pac[i][2], zac[i][2]);
            y23.y = mul2(pac[i][3], zac[i][3]);
            *(ulonglong2*)(sY + (lane + 32*i)*YLD    ) = y01;
            *(ulonglong2*)(sY + (lane + 32*i)*YLD + 4) = y23;
        }
        __syncwarp();

        // w[d] = sum_h y[h] * W1uT[h][d]   (d = 2*lane, 2*lane+1)
        ull w0p[4] = {0,0,0,0}, w1p[4] = {0,0,0,0};
        #pragma unroll 8
        for (int h = 0; h < HH; h++) {
            float2 wv = *(const float2*)(sW1uT + h*W1UT_LD + 2*lane);
            ull wa = dup2(wv.x), wb = dup2(wv.y);
            ulonglong2 ya = *(const ulonglong2*)(sY + h*YLD);
            ulonglong2 yb = *(const ulonglong2*)(sY + h*YLD + 4);
            w0p[0] = fma2(ya.x, wa, w0p[0]);  w1p[0] = fma2(ya.x, wb, w1p[0]);
            w0p[1] = fma2(ya.y, wa, w0p[1]);  w1p[1] = fma2(ya.y, wb, w1p[1]);
            w0p[2] = fma2(yb.x, wa, w0p[2]);  w1p[2] = fma2(yb.x, wb, w1p[2]);
            w0p[3] = fma2(yb.y, wa, w0p[3]);  w1p[3] = fma2(yb.y, wb, w1p[3]);
        }

        // logdet partial (per-lane, reduced after the loop)
        float ck = ((k & 1) ? -1.f : 1.f) / (float)(k + 1);
        ull ckp = dup2(ck);
        #pragma unroll
        for (int j = 0; j < 4; j++)
            lgdp[j] = fma2(ckp, fma2(w1p[j], veyp[j], mul2(w0p[j], vexp[j])), lgdp[j]);

        if (k < NPS - 1) {
            __syncwarp();
            ulonglong2 s0, s1, s2, s3;
            s0.x = w0p[0]; s0.y = w0p[1]; s1.x = w0p[2]; s1.y = w0p[3];
            s2.x = w1p[0]; s2.y = w1p[1]; s3.x = w1p[2]; s3.y = w1p[3];
            *(ulonglong2*)(sW + (2*lane  )*YLD    ) = s0;
            *(ulonglong2*)(sW + (2*lane  )*YLD + 4) = s1;
            *(ulonglong2*)(sW + (2*lane+1)*YLD    ) = s2;
            *(ulonglong2*)(sW + (2*lane+1)*YLD + 4) = s3;
            __syncwarp();

            // p[h] = sum_d w[d] * W2t[d][h]
            #pragma unroll
            for (int i = 0; i < 8; i++)
                #pragma unroll
                for (int j = 0; j < 4; j++) pac[i][j] = 0ull;

            #pragma unroll 4
            for (int d = 0; d < DD; d++) {
                ull wtp[8];
                #pragma unroll
                for (int i = 0; i < 8; i++) wtp[i] = dup2(sW2t[d*W2T_LD + lane + 32*i]);
                ulonglong2 wA = *(const ulonglong2*)(sW + d*YLD);
                ulonglong2 wB = *(const ulonglong2*)(sW + d*YLD + 4);
                ull wp[4] = {wA.x, wA.y, wB.x, wB.y};
                #pragma unroll
                for (int i = 0; i < 8; i++)
                    #pragma unroll
                    for (int j = 0; j < 4; j++)
                        pac[i][j] = fma2(wp[j], wtp[i], pac[i][j]);
            }
        }
    }

    // ---- reduce logdet partials over lanes; output[2]
    {
        float lgd[RR];
        #pragma unroll
        for (int j = 0; j < 4; j++) unpack2(lgdp[j], lgd[2*j], lgd[2*j+1]);
        #pragma unroll
        for (int r = 0; r < RR; r++) {
            float part = lgd[r];
            part += __shfl_xor_sync(0xffffffffu, part, 16);
            part += __shfl_xor_sync(0xffffffffu, part, 8);
            part += __shfl_xor_sync(0xffffffffu, part, 4);
            part += __shfl_xor_sync(0xffffffffu, part, 2);
            part += __shfl_xor_sync(0xffffffffu, part, 1);
            lgd[r] = part;
        }
        if (lane == 0) {
            float* olp = out + (size_t)2*B*DD;
            #pragma unroll
            for (int r = 0; r < RR; r++) {
                int row = row0 + r;
                olp[row] = glp[row] - lgd[r];
            }
        }
    }
}

extern "C" void kernel_launch(void* const* d_in, const int* in_sizes, int n_in,
                              void* d_out, int out_size)
{
    const float* gx   = (const float*)d_in[0];
    const float* gu   = (const float*)d_in[1];
    const float* glp  = (const float*)d_in[2];
    const float* gve  = (const float*)d_in[3];
    const float* gW1x = (const float*)d_in[4];
    const float* gW1u = (const float*)d_in[5];
    const float* gb1  = (const float*)d_in[6];
    const float* gW2  = (const float*)d_in[7];
    const float* gb2  = (const float*)d_in[8];
    float* out = (float*)d_out;

    int B = in_sizes[0] / DD;                 // 131072
    int grid = B / (NWARP*RR);                // 2048

    size_t smem = (size_t)SMEM_FLOATS * sizeof(float);   // ~210 KB
    cudaFuncSetAttribute(iresblock_kernel,
                         cudaFuncAttributeMaxDynamicSharedMemorySize, (int)smem);

    iresblock_kernel<<<grid, TPB, smem>>>(gx, gu, glp, gve, gW1x, gW1u,
                                          gb1, gW2, gb2, out, B);
}

// round 10
// speedup vs baseline: 2.6955x; 2.4301x over previous
#include <cuda_runtime.h>
#include <cuda_bf16.h>
#include <cstdint>

#define TPB 256
#define NPS 10
#define O_W1UH 0
#define O_W1UL 32768
#define O_W2H  65536
#define O_W2L  98304
#define O_X    131072
#define O_W1XL 163840
#define O_SCR  198656
#define O_B1   215552
#define SMEM_TOTAL 216576

__device__ __forceinline__ uint32_t s2u(const void* p){
  uint32_t a; asm("{ .reg .u64 t; cvta.to.shared.u64 t,%1; cvt.u32.u64 %0,t; }":"=r"(a):"l"(p)); return a;
}
__device__ __forceinline__ uint32_t pk2(float lo, float hi){
  uint32_t r; asm("cvt.rn.bf16x2.f32 %0,%1,%2;":"=r"(r):"f"(hi),"f"(lo)); return r;
}
__device__ __forceinline__ void pkhl(float a, float b, uint32_t& h, uint32_t& l){
  h = pk2(a, b);
  float ah = __uint_as_float(h << 16), bh = __uint_as_float(h & 0xffff0000u);
  l = pk2(a - ah, b - bh);
}
__device__ __forceinline__ int swo(int r, int cb){ return r*128 + (cb ^ ((r&7)<<4)); }

#define MMA(d,a,b0,b1) asm volatile( \
  "mma.sync.aligned.m16n8k16.row.col.f32.bf16.bf16.f32 {%0,%1,%2,%3},{%4,%5,%6,%7},{%8,%9},{%0,%1,%2,%3};" \
  :"+f"((d)[0]),"+f"((d)[1]),"+f"((d)[2]),"+f"((d)[3]) \
  :"r"((a)[0]),"r"((a)[1]),"r"((a)[2]),"r"((a)[3]),"r"(b0),"r"(b1))
#define LDSM(r0,r1,r2,r3,ad) asm volatile( \
  "ldmatrix.sync.aligned.m8n8.x4.shared.b16 {%0,%1,%2,%3},[%4];" \
  :"=r"(r0),"=r"(r1),"=r"(r2),"=r"(r3):"r"(ad))
#define LDSMT(r0,r1,r2,r3,ad) asm volatile( \
  "ldmatrix.sync.aligned.m8n8.x4.trans.shared.b16 {%0,%1,%2,%3},[%4];" \
  :"=r"(r0),"=r"(r1),"=r"(r2),"=r"(r3):"r"(ad))

// p[m, wg-half 128 h] = A(aH/aL, k=64) @ W2^T   (plain ldmatrix on [h][d] tile)
#define PGEMM() do { \
  _Pragma("unroll") for (int i_=0;i_<64;i_++) p[i_]=0.f; \
  _Pragma("unroll") for (int tp=0;tp<8;tp++){ int hb=wg*128+16*tp; \
    _Pragma("unroll") for (int j=0;j<4;j++){ uint32_t b0,b1,b2,b3,c0,c1,c2,c3; \
      LDSM(b0,b1,b2,b3, smb+O_W2H+swo(hb+prow,32*j+pcol)); \
      LDSM(c0,c1,c2,c3, smb+O_W2L+swo(hb+prow,32*j+pcol)); \
      MMA(p+8*tp,  aH+4*j,b0,b1); MMA(p+8*tp,  aL+4*j,b0,b1); MMA(p+8*tp,  aH+4*j,c0,c1); \
      MMA(p+8*tp+4,aH+4*j,b2,b3); MMA(p+8*tp+4,aL+4*j,b2,b3); MMA(p+8*tp+4,aH+4*j,c2,c3); \
  } } } while(0)

// w[m,64 d] partial over wg's 128 h  (trans ldmatrix on [h][d] tile)
#define WGEMM(BH,BL,AHh,ALl) do { \
  _Pragma("unroll") for (int i_=0;i_<32;i_++) w[i_]=0.f; \
  _Pragma("unroll") for (int j2=0;j2<8;j2++){ int kb=wg*128+16*j2; \
    _Pragma("unroll") for (int np=0;np<4;np++){ uint32_t b0,b1,b2,b3,c0,c1,c2,c3; \
      LDSMT(b0,b1,b2,b3, smb+(BH)+swo(kb+trow,32*np+tcol)); \
      LDSMT(c0,c1,c2,c3, smb+(BL)+swo(kb+trow,32*np+tcol)); \
      MMA(w+8*np,  (AHh)+4*j2,b0,b1); MMA(w+8*np,  (ALl)+4*j2,b0,b1); MMA(w+8*np,  (AHh)+4*j2,c0,c1); \
      MMA(w+8*np+4,(AHh)+4*j2,b2,b3); MMA(w+8*np+4,(ALl)+4*j2,b2,b3); MMA(w+8*np+4,(AHh)+4*j2,c2,c3); \
  } } } while(0)

#define SCR_ST() do { _Pragma("unroll") for (int nt=0;nt<8;nt++){ int col=8*nt+2*tig; \
  *(float2*)(scr+rl*66+col)     = make_float2(w[4*nt],  w[4*nt+1]); \
  *(float2*)(scr+(rl+8)*66+col) = make_float2(w[4*nt+2],w[4*nt+3]); } } while(0)
#define SCR_ADD() do { _Pragma("unroll") for (int nt=0;nt<8;nt++){ int col=8*nt+2*tig; \
  float2 pa=*(const float2*)(scr+rl*66+col), pb=*(const float2*)(scr+(rl+8)*66+col); \
  w[4*nt]+=pa.x; w[4*nt+1]+=pa.y; w[4*nt+2]+=pb.x; w[4*nt+3]+=pb.y; } } while(0)
#define SCR_LD() do { _Pragma("unroll") for (int nt=0;nt<8;nt++){ int col=8*nt+2*tig; \
  float2 pa=*(const float2*)(scr+rl*66+col), pb=*(const float2*)(scr+(rl+8)*66+col); \
  w[4*nt]=pa.x; w[4*nt+1]=pa.y; w[4*nt+2]=pb.x; w[4*nt+3]=pb.y; } } while(0)
#define PACK_A(src) do { _Pragma("unroll") for (int j=0;j<4;j++){ \
  pkhl((src)[8*j],  (src)[8*j+1], aH[4*j],  aL[4*j]); \
  pkhl((src)[8*j+2],(src)[8*j+3], aH[4*j+1],aL[4*j+1]); \
  pkhl((src)[8*j+4],(src)[8*j+5], aH[4*j+2],aL[4*j+2]); \
  pkhl((src)[8*j+6],(src)[8*j+7], aH[4*j+3],aL[4*j+3]); } } while(0)

__global__ __launch_bounds__(TPB, 1)
void irb(const float* __restrict__ gx,  const float* __restrict__ gu,
         const float* __restrict__ glp, const float* __restrict__ gve,
         const float* __restrict__ gW1x,const float* __restrict__ gW1u,
         const float* __restrict__ gb1, const float* __restrict__ gW2,
         const float* __restrict__ gb2, float* __restrict__ out, int B)
{
  extern __shared__ char sm[];
  const uint32_t smb = s2u(sm);
  const int tid = threadIdx.x, lane = tid & 31, warp = tid >> 5;
  const int wg = warp >> 2, wr = warp & 3, g = lane >> 2, tig = lane & 3;
  const int rl = wr*16 + g;
  const int growl = blockIdx.x*64 + rl;
  float* scr = (float*)(sm + O_SCR);
  float* sB1 = (float*)(sm + O_B1);

  // weights -> smem bf16 hi/lo, [h][d] 128B rows, XOR swizzle
  __nv_bfloat16* s16 = (__nv_bfloat16*)sm;
  for (int i = tid; i < 256*64; i += TPB) {          // W2 [H][D]
    int h = i >> 6, d = i & 63, o = swo(h, 2*d) >> 1;
    float v = gW2[i];
    __nv_bfloat16 bh = __float2bfloat16_rn(v);
    s16[(O_W2H>>1)+o] = bh;
    s16[(O_W2L>>1)+o] = __float2bfloat16_rn(v - __bfloat162float(bh));
  }
  for (int i = tid; i < 64*256; i += TPB) {          // W1u, W1x [D][H] -> [h][d]
    int d = i >> 8, h = i & 255, o = swo(h, 2*d) >> 1;
    float v = gW1u[i];
    __nv_bfloat16 bh = __float2bfloat16_rn(v);
    s16[(O_W1UH>>1)+o] = bh;
    s16[(O_W1UL>>1)+o] = __float2bfloat16_rn(v - __bfloat162float(bh));
    float w_ = gW1x[i];
    __nv_bfloat16 wh = __float2bfloat16_rn(w_);
    s16[(O_X>>1)+o] = wh;
    s16[(O_W1XL>>1)+o] = __float2bfloat16_rn(w_ - __bfloat162float(wh));
  }
  for (int i = tid; i < 256; i += TPB) sB1[i] = gb1[i];
  {
    const float4* xs = (const float4*)(gx + (size_t)blockIdx.x*64*64);
    float4* xo = (float4*)(out + (size_t)blockIdx.x*64*64);
    for (int i = tid; i < 64*16; i += TPB) xo[i] = xs[i];
  }

  // ve in C-fragment layout
  float vC[32];
  {
    const float* v0 = gve + (size_t)growl*64;
    #pragma unroll
    for (int nt = 0; nt < 8; nt++) {
      float2 a = *(const float2*)(v0 + 8*nt + 2*tig);
      float2 b = *(const float2*)(v0 + 512 + 8*nt + 2*tig);
      vC[4*nt] = a.x; vC[4*nt+1] = a.y; vC[4*nt+2] = b.x; vC[4*nt+3] = b.y;
    }
  }
  // xu A-fragments hi/lo, k = [x | u]
  uint32_t xh[32], xl[32];
  #pragma unroll
  for (int j = 0; j < 8; j++) {
    const float* src = (j < 4 ? gx : gu) + (size_t)growl*64 + 16*(j & 3);
    float2 v0 = *(const float2*)(src + 2*tig);
    float2 v1 = *(const float2*)(src + 512 + 2*tig);
    float2 v2 = *(const float2*)(src + 8 + 2*tig);
    float2 v3 = *(const float2*)(src + 512 + 8 + 2*tig);
    pkhl(v0.x,v0.y, xh[4*j],  xl[4*j]);   pkhl(v1.x,v1.y, xh[4*j+1],xl[4*j+1]);
    pkhl(v2.x,v2.y, xh[4*j+2],xl[4*j+2]); pkhl(v3.x,v3.y, xh[4*j+3],xl[4*j+3]);
  }
  __syncthreads();

  const int prow = (lane&7) + ((lane>>4)&1)*8, pcol = ((lane>>3)&1)*16;
  const int trow = (lane&7) + ((lane>>3)&1)*8, tcol = ((lane>>4)&1)*16;

  // z-GEMM into p[]
  float p[64];
  #pragma unroll
  for (int i = 0; i < 64; i++) p[i] = 0.f;
  #pragma unroll
  for (int j = 0; j < 8; j++) {
    uint32_t bh_ = smb + (j < 4 ? O_X    : O_W1UH);
    uint32_t bl_ = smb + (j < 4 ? O_W1XL : O_W1UL);
    int jb = 32*(j & 3);
    #pragma unroll
    for (int tp = 0; tp < 8; tp++) {
      int hb = wg*128 + 16*tp;
      uint32_t b0,b1,b2,b3,c0,c1,c2,c3;
      LDSM(b0,b1,b2,b3, bh_ + swo(hb+prow, jb+pcol));
      LDSM(c0,c1,c2,c3, bl_ + swo(hb+prow, jb+pcol));
      MMA(p+8*tp,  xh+4*j,b0,b1); MMA(p+8*tp,  xl+4*j,b0,b1); MMA(p+8*tp,  xh+4*j,c0,c1);
      MMA(p+8*tp+4,xh+4*j,b2,b3); MMA(p+8*tp+4,xl+4*j,b2,b3); MMA(p+8*tp+4,xh+4*j,c2,c3);
    }
  }
  __syncthreads();   // W1x region becomes s slab

  // activation: s -> per-thread slab, ha -> A-fragments
  float* sS = (float*)(sm + O_X) + tid*66;
  uint32_t hah[32], hal[32];
  #pragma unroll
  for (int nt = 0; nt < 16; nt++) {
    int col = wg*128 + 8*nt + 2*tig;
    float2 bv = *(const float2*)(sB1 + col);
    float s4[4], ha4[4];
    #pragma unroll
    for (int e = 0; e < 4; e++) {
      float zz = p[4*nt+e] + ((e & 1) ? bv.y : bv.x);
      float ex = __expf(zz);
      s4[e]  = zz > 0.f ? 1.f : ex;
      ha4[e] = zz > 0.f ? zz  : ex - 1.f;
    }
    *(float2*)(sS + 4*nt)     = make_float2(s4[0], s4[1]);
    *(float2*)(sS + 4*nt + 2) = make_float2(s4[2], s4[3]);
    int o = 4*(nt >> 1) + (nt & 1)*2;
    pkhl(ha4[0], ha4[1], hah[o],   hal[o]);
    pkhl(ha4[2], ha4[3], hah[o+1], hal[o+1]);
  }

  // g-GEMM (split-K over h-halves)
  float w[32];
  WGEMM(O_W2H, O_W2L, hah, hal);
  if (wg == 1) SCR_ST();
  __syncthreads();
  if (wg == 0) {      // v = u + g + b2
    SCR_ADD();
    const float* u0 = gu + (size_t)growl*64;
    float* vo = out + (size_t)B*64 + (size_t)growl*64;
    #pragma unroll
    for (int nt = 0; nt < 8; nt++) {
      int col = 8*nt + 2*tig;
      float2 ua = *(const float2*)(u0 + col);
      float2 ub = *(const float2*)(u0 + 512 + col);
      float2 bb = *(const float2*)(gb2 + col);
      *(float2*)(vo + col)       = make_float2(ua.x + w[4*nt]   + bb.x, ua.y + w[4*nt+1] + bb.y);
      *(float2*)(vo + 512 + col) = make_float2(ub.x + w[4*nt+2] + bb.x, ub.y + w[4*nt+3] + bb.y);
    }
  }
  __syncthreads();

  // p1 = ve @ W2^T
  uint32_t aH[16], aL[16];
  PACK_A(vC);
  PGEMM();

  // power series
  float lgdl = 0.f, lgdh = 0.f;
  #pragma unroll 1
  for (int k = 1; k <= NPS; k++) {
    uint32_t yh[32], yl[32];
    #pragma unroll
    for (int nt = 0; nt < 16; nt++) {
      float2 sa = *(const float2*)(sS + 4*nt);
      float2 sb = *(const float2*)(sS + 4*nt + 2);
      int o = 4*(nt >> 1) + (nt & 1)*2;
      pkhl(p[4*nt]*sa.x,   p[4*nt+1]*sa.y, yh[o],   yl[o]);
      pkhl(p[4*nt+2]*sb.x, p[4*nt+3]*sb.y, yh[o+1], yl[o+1]);
    }
    WGEMM(O_W1UH, O_W1UL, yh, yl);
    if (wg == 1) SCR_ST();
    __syncthreads();
    if (wg == 0) {
      SCR_ADD();
      float dl = 0.f, dh = 0.f;
      #pragma unroll
      for (int nt = 0; nt < 8; nt++) {
        dl = fmaf(w[4*nt],   vC[4*nt],   fmaf(w[4*nt+1], vC[4*nt+1], dl));
        dh = fmaf(w[4*nt+2], vC[4*nt+2], fmaf(w[4*nt+3], vC[4*nt+3], dh));
      }
      dl += __shfl_xor_sync(0xffffffffu, dl, 1); dl += __shfl_xor_sync(0xffffffffu, dl, 2);
      dh += __shfl_xor_sync(0xffffffffu, dh, 1); dh += __shfl_xor_sync(0xffffffffu, dh, 2);
      float ck = ((k & 1) ? 1.f : -1.f) / (float)k;
      lgdl = fmaf(ck, dl, lgdl); lgdh = fmaf(ck, dh, lgdh);
    }
    if (k < NPS) {
      if (wg == 0) SCR_ST();
      __syncthreads();
      if (wg == 1) SCR_LD();
      PACK_A(w);
      PGEMM();
    }
  }

  if (wg == 0 && tig == 0) {
    out[(size_t)2*B*64 + growl]     = glp[growl]     - lgdl;
    out[(size_t)2*B*64 + growl + 8] = glp[growl + 8] - lgdh;
  }
}

extern "C" void kernel_launch(void* const* d_in, const int* in_sizes, int n_in,
                              void* d_out, int out_size)
{
  const float* gx   = (const float*)d_in[0];
  const float* gu   = (const float*)d_in[1];
  const float* glp  = (const float*)d_in[2];
  const float* gve  = (const float*)d_in[3];
  const float* gW1x = (const float*)d_in[4];
  const float* gW1u = (const float*)d_in[5];
  const float* gb1  = (const float*)d_in[6];
  const float* gW2  = (const float*)d_in[7];
  const float* gb2  = (const float*)d_in[8];
  float* out = (float*)d_out;

  int B = in_sizes[0] / 64;          // 131072
  int grid = B / 64;                 // 2048

  cudaFuncSetAttribute(irb, cudaFuncAttributeMaxDynamicSharedMemorySize, SMEM_TOTAL);
  irb<<<grid, TPB, SMEM_TOTAL>>>(gx, gu, glp, gve, gW1x, gW1u, gb1, gW2, gb2, out, B);
}